// round 4
// baseline (speedup 1.0000x reference)
#include <cuda_runtime.h>
#include <cuda_bf16.h>

// Problem constants
#define NB    4
#define NC    2000      // curves per batch
#define NLS   2000      // line samples per batch
#define NS    4000      // surfaces per batch
#define NF    8000      // faces per batch
#define NTS   26000     // triangle samples per batch
#define NPT   (NC + NLS + NS + NTS)   // 34000 points per batch
#define OG    258       // occ grid edge (256 + 2*2 pad - 3 + 1)
#define X_ELEMS   (NB * NPT * 3)               // 408000
#define OCC_PER_B ((long)OG * OG * OG)         // 17,173,512
#define OCC_ELEMS (NB * OCC_PER_B)             // 68,669,448

// ---------------------------------------------------------------------------
// Kernel 1: zero the occ region (poisoned by the harness). 16B vector stores.
// ---------------------------------------------------------------------------
__global__ void zero_occ_kernel(float4* __restrict__ p, int n4) {
    int i = blockIdx.x * blockDim.x + threadIdx.x;
    if (i < n4) p[i] = make_float4(0.f, 0.f, 0.f, 0.f);
}

// ---------------------------------------------------------------------------
// Kernel 2: one thread per point. Computes the point (exact f32 op order of
// the reference, no FMA contraction), writes x, and scatters the 3x3x3
// dilated occupancy block directly into occ (dilation == padded 3-maxpool
// of the one-hot grid; coords always in-bounds, writes idempotent 1.0f).
// ---------------------------------------------------------------------------
__device__ __forceinline__ int cube_coord(float p) {
    float t = __fadd_rn(__fmul_rn(p, 256.0f), 128.5f);
    t = fminf(255.0f, fmaxf(0.0f, t));
    return (int)t;   // truncation toward zero; t >= 0 so == floor
}

__global__ void points_kernel(const float* __restrict__ curves,
                              const float* __restrict__ surfaces,
                              const float* __restrict__ t_line,
                              const float* __restrict__ uv,
                              const int*   __restrict__ lines_array,
                              const int*   __restrict__ faces_array,
                              const int*   __restrict__ line_choice,
                              const int*   __restrict__ tri_choice,
                              float* __restrict__ out) {
    int idx = blockIdx.x * blockDim.x + threadIdx.x;
    if (idx >= NB * NPT) return;
    int b = idx / NPT;
    int j = idx - b * NPT;

    float p0, p1, p2;

    if (j < NC) {
        // segment 0: curves passthrough
        const float* c = curves + ((long)(b * NC + j)) * 3;
        p0 = c[0]; p1 = c[1]; p2 = c[2];
    } else if (j < NC + NLS) {
        // segment 1: line interpolation  a + t*(b-a)
        int jj = j - NC;
        int lc = line_choice[b * NLS + jj];
        int s0 = lines_array[((long)(b * NC + lc)) * 2 + 0];
        int s1 = lines_array[((long)(b * NC + lc)) * 2 + 1];
        const float* A  = curves + ((long)(b * NC + s0)) * 3;
        const float* Bp = curves + ((long)(b * NC + s1)) * 3;
        float t = t_line[b * NLS + jj];
        p0 = __fadd_rn(A[0], __fmul_rn(t, __fsub_rn(Bp[0], A[0])));
        p1 = __fadd_rn(A[1], __fmul_rn(t, __fsub_rn(Bp[1], A[1])));
        p2 = __fadd_rn(A[2], __fmul_rn(t, __fsub_rn(Bp[2], A[2])));
    } else if (j < NC + NLS + NS) {
        // segment 2: surfaces passthrough
        int jj = j - (NC + NLS);
        const float* s = surfaces + ((long)(b * NS + jj)) * 3;
        p0 = s[0]; p1 = s[1]; p2 = s[2];
    } else {
        // segment 3: triangle barycentric sample
        int jj = j - (NC + NLS + NS);
        int tc = tri_choice[b * NTS + jj];
        const int* f = faces_array + ((long)(b * NF + tc)) * 3;
        const float* ta = surfaces + ((long)(b * NS + f[0])) * 3;
        const float* tb = surfaces + ((long)(b * NS + f[1])) * 3;
        const float* tcx = surfaces + ((long)(b * NS + f[2])) * 3;
        float u = uv[((long)(b * NTS + jj)) * 2 + 0];
        float v = uv[((long)(b * NTS + jj)) * 2 + 1];
        if (__fadd_rn(u, v) > 1.0f) {
            u = __fsub_rn(1.0f, u);
            v = __fsub_rn(1.0f, v);
        }
        // (ta + u*(tb-ta)) + v*(tc-ta), exact reference op order
        p0 = __fadd_rn(__fadd_rn(ta[0], __fmul_rn(u, __fsub_rn(tb[0], ta[0]))),
                       __fmul_rn(v, __fsub_rn(tcx[0], ta[0])));
        p1 = __fadd_rn(__fadd_rn(ta[1], __fmul_rn(u, __fsub_rn(tb[1], ta[1]))),
                       __fmul_rn(v, __fsub_rn(tcx[1], ta[1])));
        p2 = __fadd_rn(__fadd_rn(ta[2], __fmul_rn(u, __fsub_rn(tb[2], ta[2]))),
                       __fmul_rn(v, __fsub_rn(tcx[2], ta[2])));
    }

    // write x
    float* xo = out + ((long)(b * NPT + j)) * 3;
    xo[0] = p0; xo[1] = p1; xo[2] = p2;

    // voxel coord
    int c0 = cube_coord(p0);
    int c1 = cube_coord(p1);
    int c2 = cube_coord(p2);

    // scatter dilated 3x3x3 block: occ[b, c0..c0+2, c1..c1+2, c2..c2+2] = 1
    // c in [0,255] -> output coords in [0,257], always in-bounds.
    float* occ = out + X_ELEMS + (long)b * OCC_PER_B;
    #pragma unroll
    for (int d0 = 0; d0 < 3; d0++) {
        long base0 = (long)(c0 + d0) * (OG * OG);
        #pragma unroll
        for (int d1 = 0; d1 < 3; d1++) {
            float* row = occ + base0 + (long)(c1 + d1) * OG + c2;
            row[0] = 1.0f; row[1] = 1.0f; row[2] = 1.0f;
        }
    }
}

extern "C" void kernel_launch(void* const* d_in, const int* in_sizes, int n_in,
                              void* d_out, int out_size) {
    // metadata order:
    // 0 imgs (unused), 1 curves, 2 surfaces, 3 t_line, 4 uv,
    // 5 lines_array, 6 faces_array, 7 indices_array (unused),
    // 8 line_choice, 9 tri_choice
    const float* curves      = (const float*)d_in[1];
    const float* surfaces    = (const float*)d_in[2];
    const float* t_line      = (const float*)d_in[3];
    const float* uv          = (const float*)d_in[4];
    const int*   lines_array = (const int*)d_in[5];
    const int*   faces_array = (const int*)d_in[6];
    const int*   line_choice = (const int*)d_in[8];
    const int*   tri_choice  = (const int*)d_in[9];
    float* out = (float*)d_out;

    // zero occ region (68,669,448 floats, divisible by 4; base offset
    // 408000 floats = 1,632,000 bytes, 16B-aligned)
    int n4 = (int)(OCC_ELEMS / 4);
    int zb = (n4 + 255) / 256;
    zero_occ_kernel<<<zb, 256>>>((float4*)(out + X_ELEMS), n4);

    int npts = NB * NPT;
    int pb = (npts + 255) / 256;
    points_kernel<<<pb, 256>>>(curves, surfaces, t_line, uv,
                               lines_array, faces_array,
                               line_choice, tri_choice, out);
}

// round 6
// speedup vs baseline: 1.0365x; 1.0365x over previous
#include <cuda_runtime.h>
#include <cuda_bf16.h>

// Problem constants
#define NB    4
#define NC    2000      // curves per batch
#define NLS   2000      // line samples per batch
#define NS    4000      // surfaces per batch
#define NF    8000      // faces per batch
#define NTS   26000     // triangle samples per batch
#define NPT   (NC + NLS + NS + NTS)   // 34000 points per batch
#define NPTOT (NB * NPT)              // 136000 points total
#define OG    258       // occ grid edge (256 + 2*2 pad - 3 + 1)
#define X_ELEMS   (NB * NPT * 3)               // 408000
#define OCC_PER_B ((long)OG * OG * OG)         // 17,173,512
#define OCC_ELEMS (NB * OCC_PER_B)             // 68,669,448

// Scratch: packed voxel coords per point (c0 | c1<<8 | c2<<16).
__device__ int g_coords[NPTOT];

// ---------------------------------------------------------------------------
// Kernel 1: zero the occ region. 16B vector stores; already at ~6.4 TB/s
// (near the HBM write ceiling) — this is the structural floor.
// ---------------------------------------------------------------------------
__global__ void zero_occ_kernel(float4* __restrict__ p, int n4) {
    int i = blockIdx.x * blockDim.x + threadIdx.x;
    if (i < n4) p[i] = make_float4(0.f, 0.f, 0.f, 0.f);
}

// ---------------------------------------------------------------------------
// Kernel 2: one thread per point. Computes the point with the exact f32 op
// order of the reference (no FMA contraction), writes x, writes packed coord.
// ---------------------------------------------------------------------------
__device__ __forceinline__ int cube_coord(float p) {
    float t = __fadd_rn(__fmul_rn(p, 256.0f), 128.5f);
    t = fminf(255.0f, fmaxf(0.0f, t));
    return (int)t;   // t >= 0 so truncation == floor
}

__global__ void points_kernel(const float* __restrict__ curves,
                              const float* __restrict__ surfaces,
                              const float* __restrict__ t_line,
                              const float* __restrict__ uv,
                              const int*   __restrict__ lines_array,
                              const int*   __restrict__ faces_array,
                              const int*   __restrict__ line_choice,
                              const int*   __restrict__ tri_choice,
                              float* __restrict__ out) {
    int idx = blockIdx.x * blockDim.x + threadIdx.x;
    if (idx >= NPTOT) return;
    int b = idx / NPT;
    int j = idx - b * NPT;

    float p0, p1, p2;

    if (j < NC) {
        // segment 0: curves passthrough
        const float* c = curves + ((long)(b * NC + j)) * 3;
        p0 = c[0]; p1 = c[1]; p2 = c[2];
    } else if (j < NC + NLS) {
        // segment 1: line interpolation  a + t*(b-a)
        int jj = j - NC;
        int lc = line_choice[b * NLS + jj];
        int s0 = lines_array[((long)(b * NC + lc)) * 2 + 0];
        int s1 = lines_array[((long)(b * NC + lc)) * 2 + 1];
        const float* A  = curves + ((long)(b * NC + s0)) * 3;
        const float* Bp = curves + ((long)(b * NC + s1)) * 3;
        float t = t_line[b * NLS + jj];
        p0 = __fadd_rn(A[0], __fmul_rn(t, __fsub_rn(Bp[0], A[0])));
        p1 = __fadd_rn(A[1], __fmul_rn(t, __fsub_rn(Bp[1], A[1])));
        p2 = __fadd_rn(A[2], __fmul_rn(t, __fsub_rn(Bp[2], A[2])));
    } else if (j < NC + NLS + NS) {
        // segment 2: surfaces passthrough
        int jj = j - (NC + NLS);
        const float* s = surfaces + ((long)(b * NS + jj)) * 3;
        p0 = s[0]; p1 = s[1]; p2 = s[2];
    } else {
        // segment 3: triangle barycentric sample
        int jj = j - (NC + NLS + NS);
        int tc = tri_choice[b * NTS + jj];
        const int* f = faces_array + ((long)(b * NF + tc)) * 3;
        const float* ta  = surfaces + ((long)(b * NS + f[0])) * 3;
        const float* tb  = surfaces + ((long)(b * NS + f[1])) * 3;
        const float* tcx = surfaces + ((long)(b * NS + f[2])) * 3;
        float u = uv[((long)(b * NTS + jj)) * 2 + 0];
        float v = uv[((long)(b * NTS + jj)) * 2 + 1];
        if (__fadd_rn(u, v) > 1.0f) {
            u = __fsub_rn(1.0f, u);
            v = __fsub_rn(1.0f, v);
        }
        // (ta + u*(tb-ta)) + v*(tc-ta), exact reference op order
        p0 = __fadd_rn(__fadd_rn(ta[0], __fmul_rn(u, __fsub_rn(tb[0], ta[0]))),
                       __fmul_rn(v, __fsub_rn(tcx[0], ta[0])));
        p1 = __fadd_rn(__fadd_rn(ta[1], __fmul_rn(u, __fsub_rn(tb[1], ta[1]))),
                       __fmul_rn(v, __fsub_rn(tcx[1], ta[1])));
        p2 = __fadd_rn(__fadd_rn(ta[2], __fmul_rn(u, __fsub_rn(tb[2], ta[2]))),
                       __fmul_rn(v, __fsub_rn(tcx[2], ta[2])));
    }

    // write x
    float* xo = out + ((long)idx) * 3;
    xo[0] = p0; xo[1] = p1; xo[2] = p2;

    // packed voxel coord for the scatter kernel
    int c0 = cube_coord(p0);
    int c1 = cube_coord(p1);
    int c2 = cube_coord(p2);
    g_coords[idx] = c0 | (c1 << 8) | (c2 << 16);
}

// ---------------------------------------------------------------------------
// Kernel 3: scatter. One thread per (point, d0, d1) — 9x the parallelism of
// the fused version, so the scattered STGs are spread across ~1.2M threads
// and the LSU/scoreboard latency is hidden. Each thread writes one 3-float
// row of the dilated 3x3x3 block (dilation == padded 3-maxpool of the
// one-hot grid; coords always in-bounds, writes idempotent 1.0f).
// ---------------------------------------------------------------------------
__global__ void scatter_kernel(float* __restrict__ out) {
    int pidx = blockIdx.x * blockDim.x + threadIdx.x;
    if (pidx >= NPTOT) return;
    int r  = blockIdx.y;       // 0..8
    int d0 = r / 3;
    int d1 = r - d0 * 3;

    int packed = g_coords[pidx];           // coalesced; L2-broadcast across y
    int c0 = packed & 0xFF;
    int c1 = (packed >> 8) & 0xFF;
    int c2 = (packed >> 16) & 0xFF;
    int b  = pidx / NPT;

    float* row = out + X_ELEMS + (long)b * OCC_PER_B
               + (long)(c0 + d0) * (OG * OG)
               + (long)(c1 + d1) * OG + c2;
    row[0] = 1.0f; row[1] = 1.0f; row[2] = 1.0f;
}

extern "C" void kernel_launch(void* const* d_in, const int* in_sizes, int n_in,
                              void* d_out, int out_size) {
    // metadata order:
    // 0 imgs (unused), 1 curves, 2 surfaces, 3 t_line, 4 uv,
    // 5 lines_array, 6 faces_array, 7 indices_array (unused),
    // 8 line_choice, 9 tri_choice
    const float* curves      = (const float*)d_in[1];
    const float* surfaces    = (const float*)d_in[2];
    const float* t_line      = (const float*)d_in[3];
    const float* uv          = (const float*)d_in[4];
    const int*   lines_array = (const int*)d_in[5];
    const int*   faces_array = (const int*)d_in[6];
    const int*   line_choice = (const int*)d_in[8];
    const int*   tri_choice  = (const int*)d_in[9];
    float* out = (float*)d_out;

    // points first (independent of occ region; overlaps tail of nothing but
    // keeps the zero kernel adjacent to the scatter that depends on it)
    int pb = (NPTOT + 255) / 256;
    points_kernel<<<pb, 256>>>(curves, surfaces, t_line, uv,
                               lines_array, faces_array,
                               line_choice, tri_choice, out);

    // zero occ region (68,669,448 floats, divisible by 4; base offset
    // 408000 floats = 1,632,000 bytes, 16B-aligned)
    int n4 = (int)(OCC_ELEMS / 4);
    int zb = (n4 + 255) / 256;
    zero_occ_kernel<<<zb, 256>>>((float4*)(out + X_ELEMS), n4);

    // scatter: 9 rows per point, one thread each
    dim3 sg(pb, 9, 1);
    scatter_kernel<<<sg, 256>>>(out);
}